// round 2
// baseline (speedup 1.0000x reference)
#include <cuda_runtime.h>

// ModularTreeMLPPredictor — bottom-up per-level MLP over a heap-indexed tree.
// R1: lane-pair split (2 threads per row, 32 output cols each) + packed
// fma.rn.f32x2 + bank-conflict-free padded weight tiles in smem.
//
// Inputs (metadata order):
//   d_in[0] features  float32 [512, 2047, 32]
//   d_in[1] treatment float32 [512]
//   d_in[2] W1        float32 [11, 35, 64]
//   d_in[3] b1        float32 [11, 64]
//   d_in[4] W2        float32 [11, 64, 64]
//   d_in[5] b2        float32 [11, 64]
//   d_in[6] W3        float32 [11, 64, 1]
//   d_in[7] b3        float32 [11, 1]
// Output: float32 [512, 2047]

namespace {

constexpr int kD   = 11;
constexpr int kF   = 32;
constexpr int kH   = 64;
constexpr int kB   = 512;
constexpr int kN   = 2047;
constexpr int kFin = kF + 3; // 35

constexpr int kThreads      = 128;
constexpr int kRowsPerBlock = kThreads / 2; // 64
constexpr int kMaxGrid      = 592;          // 4 CTAs/SM * 148 SMs

// Padded row stride: halves [0..31] at words 0..31, [32..63] at words 36..67.
// The +16B gap puts the two per-warp broadcast groups on disjoint banks.
constexpr int kPadH = 72;

using ull = unsigned long long;

__device__ __forceinline__ ull pack2(float lo, float hi) {
    ull d;
    asm("mov.b64 %0, {%1, %2};" : "=l"(d) : "f"(lo), "f"(hi));
    return d;
}
__device__ __forceinline__ void unpack2(ull v, float& lo, float& hi) {
    asm("mov.b64 {%0, %1}, %2;" : "=f"(lo), "=f"(hi) : "l"(v));
}
__device__ __forceinline__ ull fma2(ull a, ull b, ull c) {
    ull d;
    asm("fma.rn.f32x2 %0, %1, %2, %3;" : "=l"(d) : "l"(a), "l"(b), "l"(c));
    return d;
}

__global__ __launch_bounds__(kThreads, 4)
void tree_level_kernel(const float* __restrict__ features,
                       const float* __restrict__ treatment,
                       const float* __restrict__ W1,
                       const float* __restrict__ b1,
                       const float* __restrict__ W2,
                       const float* __restrict__ b2,
                       const float* __restrict__ W3,
                       const float* __restrict__ b3,
                       float* __restrict__ out,
                       int level)
{
    __shared__ float sW1[kFin][kPadH];  // 10080 B
    __shared__ float sW2[kH][kPadH];    // 18432 B
    __shared__ float sb1[kH];
    __shared__ float sb2[kH];
    __shared__ float sW3[kH];
    __shared__ float sb3v;

    const int tid = threadIdx.x;

    // ---- stage weights (padded halves) ----
    {
        const float* w1l = W1 + (size_t)level * kFin * kH;
        for (int i = tid; i < kFin * kH; i += kThreads) {
            int f = i >> 6, j = i & 63;
            sW1[f][j + ((j >> 5) << 2)] = w1l[i];
        }
        const float* w2l = W2 + (size_t)level * kH * kH;
        for (int i = tid; i < kH * kH; i += kThreads) {
            int f = i >> 6, j = i & 63;
            sW2[f][j + ((j >> 5) << 2)] = w2l[i];
        }
        if (tid < kH) {
            sb1[tid] = b1[level * kH + tid];
            sb2[tid] = b2[level * kH + tid];
            sW3[tid] = W3[level * kH + tid];
        }
        if (tid == 0) sb3v = b3[level];
    }
    __syncthreads();

    const int n     = 1 << level;
    const int Mrows = kB * n;
    const bool leaf = (level == kD - 1);

    const int sub   = tid & 1;        // which 32-col half this lane owns
    const int pidx  = tid >> 1;       // row slot within block
    const int wbase = sub * 36;       // padded word offset of the half
    const int col0  = sub * 32;       // logical column base (for bias/W3)

    for (int base = blockIdx.x * kRowsPerBlock; base < Mrows;
         base += gridDim.x * kRowsPerBlock) {
        int row = base + pidx;
        const bool valid = row < Mrows;
        if (!valid) row = Mrows - 1;   // clamp: keep warp converged for shfl

        const int b = row >> level;
        const int i = row & (n - 1);
        const int g = n - 1 + i;

        // ---- gather x[35] ----
        float x[kFin];
        const float4* fptr = reinterpret_cast<const float4*>(
            features + ((size_t)b * kN + g) * kF);
        #pragma unroll
        for (int q = 0; q < kF / 4; q++) {
            float4 v = fptr[q];
            x[4 * q + 0] = v.x; x[4 * q + 1] = v.y;
            x[4 * q + 2] = v.z; x[4 * q + 3] = v.w;
        }
        if (leaf) {
            x[kF + 0] = 0.0f;
            x[kF + 1] = 0.0f;
        } else {
            const float* orow = out + (size_t)b * kN;
            x[kF + 0] = orow[2 * g + 1];
            x[kF + 1] = orow[2 * g + 2];
        }
        x[kF + 2] = treatment[b];

        // ---- layer 1: own 32 cols, packed f32x2 ----
        ull acc[16];
        {
            const ull* bp = reinterpret_cast<const ull*>(&sb1[col0]);
            #pragma unroll
            for (int q = 0; q < 16; q++) acc[q] = bp[q];
        }
        #pragma unroll
        for (int f = 0; f < kFin; f++) {
            const ull xf2 = pack2(x[f], x[f]);
            const ulonglong2* w =
                reinterpret_cast<const ulonglong2*>(&sW1[f][0] + wbase);
            #pragma unroll
            for (int q = 0; q < 8; q++) {
                ulonglong2 wv = w[q];
                acc[2 * q + 0] = fma2(xf2, wv.x, acc[2 * q + 0]);
                acc[2 * q + 1] = fma2(xf2, wv.y, acc[2 * q + 1]);
            }
        }
        float h1[32];
        #pragma unroll
        for (int q = 0; q < 16; q++) {
            float lo, hi;
            unpack2(acc[q], lo, hi);
            h1[2 * q + 0] = fmaxf(lo, 0.0f);
            h1[2 * q + 1] = fmaxf(hi, 0.0f);
        }

        // ---- layer 2: need full h1[64]; exchange halves via shfl ----
        ull acc2[16];
        {
            const ull* bp = reinterpret_cast<const ull*>(&sb2[col0]);
            #pragma unroll
            for (int q = 0; q < 16; q++) acc2[q] = bp[q];
        }
        #pragma unroll
        for (int idx = 0; idx < 32; idx++) {
            const float mine   = h1[idx];
            const float theirs = __shfl_xor_sync(0xffffffffu, mine, 1);
            const float flo = sub ? theirs : mine;   // global f = idx
            const float fhi = sub ? mine : theirs;   // global f = idx + 32
            const ull flo2 = pack2(flo, flo);
            const ull fhi2 = pack2(fhi, fhi);
            const ulonglong2* wl =
                reinterpret_cast<const ulonglong2*>(&sW2[idx][0] + wbase);
            const ulonglong2* wh =
                reinterpret_cast<const ulonglong2*>(&sW2[idx + 32][0] + wbase);
            #pragma unroll
            for (int q = 0; q < 8; q++) {
                ulonglong2 wv = wl[q];
                acc2[2 * q + 0] = fma2(flo2, wv.x, acc2[2 * q + 0]);
                acc2[2 * q + 1] = fma2(flo2, wv.y, acc2[2 * q + 1]);
            }
            #pragma unroll
            for (int q = 0; q < 8; q++) {
                ulonglong2 wv = wh[q];
                acc2[2 * q + 0] = fma2(fhi2, wv.x, acc2[2 * q + 0]);
                acc2[2 * q + 1] = fma2(fhi2, wv.y, acc2[2 * q + 1]);
            }
        }

        // ---- layer 3: partial dot over own cols, pair-reduce ----
        float y = 0.0f;
        #pragma unroll
        for (int q = 0; q < 16; q++) {
            float lo, hi;
            unpack2(acc2[q], lo, hi);
            y = fmaf(fmaxf(lo, 0.0f), sW3[col0 + 2 * q + 0], y);
            y = fmaf(fmaxf(hi, 0.0f), sW3[col0 + 2 * q + 1], y);
        }
        y += __shfl_xor_sync(0xffffffffu, y, 1);

        if (valid && sub == 0) {
            out[(size_t)b * kN + g] = y + sb3v;
        }
    }
}

} // namespace

extern "C" void kernel_launch(void* const* d_in, const int* in_sizes, int n_in,
                              void* d_out, int out_size)
{
    (void)in_sizes; (void)n_in; (void)out_size;

    const float* features  = (const float*)d_in[0];
    const float* treatment = (const float*)d_in[1];
    const float* W1        = (const float*)d_in[2];
    const float* b1        = (const float*)d_in[3];
    const float* W2        = (const float*)d_in[4];
    const float* b2        = (const float*)d_in[5];
    const float* W3        = (const float*)d_in[6];
    const float* b3        = (const float*)d_in[7];
    float*       out       = (float*)d_out;

    for (int level = kD - 1; level >= 0; level--) {
        const int Mrows = kB << level;
        int blocks = (Mrows + kRowsPerBlock - 1) / kRowsPerBlock;
        if (blocks > kMaxGrid) blocks = kMaxGrid;
        tree_level_kernel<<<blocks, kThreads>>>(
            features, treatment, W1, b1, W2, b2, W3, b3, out, level);
    }
}

// round 6
// speedup vs baseline: 2.3303x; 2.3303x over previous
#include <cuda_runtime.h>

// ModularTreeMLPPredictor — bottom-up per-level MLP over a heap-indexed tree.
// R5 == R4 (infra failure last round; resubmitting for measurement).
// Scalar FFMA, layer-2/3 in two 32-col passes (caps live regs ~105, no
// spill at __launch_bounds__(128,4)). Levels 10..8 as per-level kernels;
// levels 7..0 fused into one per-batch kernel (kills the launch tail).
//
// Inputs (metadata order):
//   d_in[0] features  float32 [512, 2047, 32]
//   d_in[1] treatment float32 [512]
//   d_in[2] W1        float32 [11, 35, 64]
//   d_in[3] b1        float32 [11, 64]
//   d_in[4] W2        float32 [11, 64, 64]
//   d_in[5] b2        float32 [11, 64]
//   d_in[6] W3        float32 [11, 64, 1]
//   d_in[7] b3        float32 [11, 1]
// Output: float32 [512, 2047]

namespace {

constexpr int kD   = 11;
constexpr int kF   = 32;
constexpr int kH   = 64;
constexpr int kB   = 512;
constexpr int kN   = 2047;
constexpr int kFin = kF + 3;    // 35
constexpr int kFuseTop = 7;     // levels kFuseTop..0 run in the fused kernel

constexpr int kThreads = 128;
constexpr int kMaxGrid = 592;   // 4 CTAs/SM * 148 SMs

// Full 35->64->64->1 MLP for one row. Weights in smem, scalar FFMA.
// Layer 2+3 computed in two 32-column passes to cap live registers.
__device__ __forceinline__ float mlp_row(const float (&x)[kFin],
                                         const float (&sW1)[kFin][kH],
                                         const float (&sW2)[kH][kH],
                                         const float* __restrict__ sb1,
                                         const float* __restrict__ sb2,
                                         const float* __restrict__ sW3,
                                         float sb3v)
{
    // ---- layer 1: h1 = relu(x @ W1 + b1) ----
    float h1[kH];
    #pragma unroll
    for (int h = 0; h < kH; h++) h1[h] = sb1[h];
    #pragma unroll
    for (int f = 0; f < kFin; f++) {
        const float xf = x[f];
        const float4* w = reinterpret_cast<const float4*>(&sW1[f][0]);
        #pragma unroll
        for (int q = 0; q < kH / 4; q++) {
            float4 wv = w[q];
            h1[4 * q + 0] = fmaf(xf, wv.x, h1[4 * q + 0]);
            h1[4 * q + 1] = fmaf(xf, wv.y, h1[4 * q + 1]);
            h1[4 * q + 2] = fmaf(xf, wv.z, h1[4 * q + 2]);
            h1[4 * q + 3] = fmaf(xf, wv.w, h1[4 * q + 3]);
        }
    }
    #pragma unroll
    for (int h = 0; h < kH; h++) h1[h] = fmaxf(h1[h], 0.0f);

    // ---- layers 2+3 in two 32-column passes (caps live registers) ----
    float y = sb3v;
    #pragma unroll
    for (int half = 0; half < 2; half++) {
        const int c0 = half * (kH / 2);   // 0 or 32

        float acc[kH / 2];
        #pragma unroll
        for (int q = 0; q < kH / 2; q++) acc[q] = sb2[c0 + q];

        #pragma unroll
        for (int f = 0; f < kH; f++) {
            const float xf = h1[f];
            const float4* w = reinterpret_cast<const float4*>(&sW2[f][c0]);
            #pragma unroll
            for (int q = 0; q < kH / 8; q++) {
                float4 wv = w[q];
                acc[4 * q + 0] = fmaf(xf, wv.x, acc[4 * q + 0]);
                acc[4 * q + 1] = fmaf(xf, wv.y, acc[4 * q + 1]);
                acc[4 * q + 2] = fmaf(xf, wv.z, acc[4 * q + 2]);
                acc[4 * q + 3] = fmaf(xf, wv.w, acc[4 * q + 3]);
            }
        }

        #pragma unroll
        for (int q = 0; q < kH / 2; q++) {
            y = fmaf(fmaxf(acc[q], 0.0f), sW3[c0 + q], y);
        }
    }
    return y;
}

// Stage one level's weights into shared memory (all threads participate).
__device__ __forceinline__ void stage_weights(int level, int tid,
                                              const float* __restrict__ W1,
                                              const float* __restrict__ b1,
                                              const float* __restrict__ W2,
                                              const float* __restrict__ b2,
                                              const float* __restrict__ W3,
                                              const float* __restrict__ b3,
                                              float (&sW1)[kFin][kH],
                                              float (&sW2)[kH][kH],
                                              float* sb1, float* sb2,
                                              float* sW3, float* sb3v)
{
    const float* w1l = W1 + (size_t)level * kFin * kH;
    float* d1 = &sW1[0][0];
    for (int i = tid; i < kFin * kH; i += kThreads) d1[i] = w1l[i];
    const float* w2l = W2 + (size_t)level * kH * kH;
    float* d2 = &sW2[0][0];
    for (int i = tid; i < kH * kH; i += kThreads) d2[i] = w2l[i];
    if (tid < kH) {
        sb1[tid] = b1[level * kH + tid];
        sb2[tid] = b2[level * kH + tid];
        sW3[tid] = W3[level * kH + tid];
    }
    if (tid == 0) *sb3v = b3[level];
}

// ---------------- big levels (10..8): one kernel per level ----------------
__global__ __launch_bounds__(kThreads, 4)
void tree_level_kernel(const float* __restrict__ features,
                       const float* __restrict__ treatment,
                       const float* __restrict__ W1,
                       const float* __restrict__ b1,
                       const float* __restrict__ W2,
                       const float* __restrict__ b2,
                       const float* __restrict__ W3,
                       const float* __restrict__ b3,
                       float* __restrict__ out,
                       int level)
{
    __shared__ float sW1[kFin][kH];
    __shared__ float sW2[kH][kH];
    __shared__ float sb1[kH];
    __shared__ float sb2[kH];
    __shared__ float sW3[kH];
    __shared__ float sb3v;

    const int tid = threadIdx.x;
    stage_weights(level, tid, W1, b1, W2, b2, W3, b3,
                  sW1, sW2, sb1, sb2, sW3, &sb3v);
    __syncthreads();

    const int  n    = 1 << level;
    const int  M    = kB * n;
    const bool leaf = (level == kD - 1);

    for (int row = blockIdx.x * kThreads + tid; row < M;
         row += gridDim.x * kThreads) {
        const int b = row >> level;
        const int i = row & (n - 1);
        const int g = n - 1 + i;

        float x[kFin];
        const float4* fptr = reinterpret_cast<const float4*>(
            features + ((size_t)b * kN + g) * kF);
        #pragma unroll
        for (int q = 0; q < kF / 4; q++) {
            float4 v = fptr[q];
            x[4 * q + 0] = v.x; x[4 * q + 1] = v.y;
            x[4 * q + 2] = v.z; x[4 * q + 3] = v.w;
        }
        if (leaf) {
            x[kF + 0] = 0.0f;
            x[kF + 1] = 0.0f;
        } else {
            const float* orow = out + (size_t)b * kN;
            x[kF + 0] = orow[2 * g + 1];
            x[kF + 1] = orow[2 * g + 2];
        }
        x[kF + 2] = treatment[b];

        out[(size_t)b * kN + g] =
            mlp_row(x, sW1, sW2, sb1, sb2, sW3, sb3v);
    }
}

// ------------- fused tail (levels 7..0): one block per batch -------------
__global__ __launch_bounds__(kThreads, 4)
void tree_tail_kernel(const float* __restrict__ features,
                      const float* __restrict__ treatment,
                      const float* __restrict__ W1,
                      const float* __restrict__ b1,
                      const float* __restrict__ W2,
                      const float* __restrict__ b2,
                      const float* __restrict__ W3,
                      const float* __restrict__ b3,
                      float* __restrict__ out)
{
    __shared__ float sW1[kFin][kH];
    __shared__ float sW2[kH][kH];
    __shared__ float sb1[kH];
    __shared__ float sb2[kH];
    __shared__ float sW3[kH];
    __shared__ float sb3v;
    __shared__ float sbuf[1 << kFuseTop];   // previous level outputs (<=128)

    const int tid = threadIdx.x;
    const int b   = blockIdx.x;
    const float t = treatment[b];

    for (int level = kFuseTop; level >= 0; level--) {
        stage_weights(level, tid, W1, b1, W2, b2, W3, b3,
                      sW1, sW2, sb1, sb2, sW3, &sb3v);

        const int n = 1 << level;
        const int g = n - 1 + tid;
        float left = 0.0f, right = 0.0f;

        // read children BEFORE the barrier (sbuf still holds level+1 outputs)
        if (tid < n) {
            if (level == kFuseTop) {
                const float* orow = out + (size_t)b * kN;
                left  = orow[2 * g + 1];   // level-8 outputs from global
                right = orow[2 * g + 2];
            } else {
                left  = sbuf[2 * tid + 0];
                right = sbuf[2 * tid + 1];
            }
        }
        __syncthreads();   // staging done; child reads done

        if (tid < n) {
            float x[kFin];
            const float4* fptr = reinterpret_cast<const float4*>(
                features + ((size_t)b * kN + g) * kF);
            #pragma unroll
            for (int q = 0; q < kF / 4; q++) {
                float4 v = fptr[q];
                x[4 * q + 0] = v.x; x[4 * q + 1] = v.y;
                x[4 * q + 2] = v.z; x[4 * q + 3] = v.w;
            }
            x[kF + 0] = left;
            x[kF + 1] = right;
            x[kF + 2] = t;

            float y = mlp_row(x, sW1, sW2, sb1, sb2, sW3, sb3v);
            sbuf[tid] = y;
            out[(size_t)b * kN + g] = y;
        }
        __syncthreads();   // sbuf + compute done before restaging weights
    }
}

} // namespace

extern "C" void kernel_launch(void* const* d_in, const int* in_sizes, int n_in,
                              void* d_out, int out_size)
{
    (void)in_sizes; (void)n_in; (void)out_size;

    const float* features  = (const float*)d_in[0];
    const float* treatment = (const float*)d_in[1];
    const float* W1        = (const float*)d_in[2];
    const float* b1        = (const float*)d_in[3];
    const float* W2        = (const float*)d_in[4];
    const float* b2        = (const float*)d_in[5];
    const float* W3        = (const float*)d_in[6];
    const float* b3        = (const float*)d_in[7];
    float*       out       = (float*)d_out;

    for (int level = kD - 1; level > kFuseTop; level--) {
        const int M = kB << level;
        int blocks  = (M + kThreads - 1) / kThreads;
        if (blocks > kMaxGrid) blocks = kMaxGrid;
        tree_level_kernel<<<blocks, kThreads>>>(
            features, treatment, W1, b1, W2, b2, W3, b3, out, level);
    }
    tree_tail_kernel<<<kB, kThreads>>>(
        features, treatment, W1, b1, W2, b2, W3, b3, out);
}